// round 8
// baseline (speedup 1.0000x reference)
#include <cuda_runtime.h>
#include <cstddef>
#include <cstring>

#define Bv 32
#define Tv 512
#define Cv 8
#define Hv 256
#define Gv 1024

// ---------------- scratch (device globals: allocation-free) ----------------
__device__ float g_h1[(size_t)Tv * Cv * Hv * Bv];   // layer1 hidden, [T][C][H][B]
__device__ float g_hbuf[2 * Cv * Hv * Bv];          // h exchange, [2][C][H][B]
__device__ unsigned g_cnt[Cv];                      // per-channel barrier counters (zero-init)
__device__ unsigned g_sense[Cv];                    // per-channel barrier sense (zero-init)

// ---------------- math helpers ----------------
__device__ __forceinline__ float sig_(float x) {
    return __fdividef(1.0f, 1.0f + __expf(-x));
}
__device__ __forceinline__ float tanh_(float x) {
    float ax = fabsf(x);
    float e  = __expf(-2.0f * ax);
    float t  = __fdividef(1.0f - e, 1.0f + e);
    return copysignf(t, x);
}
__device__ __forceinline__ float2 u2f(unsigned long long u) {
    float2 f; memcpy(&f, &u, 8); return f;
}

// packed fp32x2 ops
#define FMA2(acc, h, w) asm("fma.rn.f32x2 %0, %1, %2, %0;" : "+l"(acc) : "l"(h), "l"(w))
#define ADD2(d, a, b)   asm("add.rn.f32x2 %0, %1, %2;" : "=l"(d) : "l"(a), "l"(b))
#define PACK2(d, s)     asm("mov.b64 %0, {%1, %1};" : "=l"(d) : "f"(s))

// cp.async helpers
__device__ __forceinline__ unsigned smem_u32(const void* p) {
    unsigned r;
    asm("{ .reg .u64 t; cvta.to.shared.u64 t, %1; cvt.u32.u64 %0, t; }" : "=r"(r) : "l"(p));
    return r;
}
__device__ __forceinline__ void cp16(unsigned s, const void* g) {
    asm volatile("cp.async.cg.shared.global [%0], [%1], 16;" :: "r"(s), "l"(g));
}
#define CP_COMMIT() asm volatile("cp.async.commit_group;" ::: "memory")
#define CP_WAIT0()  asm volatile("cp.async.wait_group 0;" ::: "memory")

// per-channel sense-reversing barrier across the 16 CTAs of a channel (R4/R7-proven)
__device__ __forceinline__ void chan_barrier(int c, unsigned &lsense) {
    __syncthreads();
    if (threadIdx.x == 0) {
        __threadfence();
        unsigned a = atomicAdd(&g_cnt[c], 1u);
        if (a == 15u) {
            *(volatile unsigned*)&g_cnt[c] = 0u;
            __threadfence();
            *(volatile unsigned*)&g_sense[c] = lsense ^ 1u;
        } else {
            while (*(volatile unsigned*)&g_sense[c] == lsense) { __nanosleep(20); }
            __threadfence();
        }
    }
    lsense ^= 1u;
    __syncthreads();
}

// ---------------- smem layout (floats) ----------------
// Whh_s [256][64] : 16384 | Wih_s [256][64] : 16384 (L2)
// h_s [256][32] : 8192 | h1_s [256][32] : 8192 (L2)
// parts: 4 x [32][66] = 8448 (per-kq partial gate sums)
// wlin_s 256 | wih1s 64 | xs 32       (ored aliases parts)
#define GSTR 66
#define PBUF 2112
#define SM_FLOATS (16384 + 16384 + 8192 + 8192 + 4 * PBUF + 256 + 64 + 32)
#define SM_BYTES  (SM_FLOATS * 4)   // 231808 B < 227 KB

template <int LAYER>
__global__ __launch_bounds__(512, 1)
void lstm_kernel(const float* __restrict__ x,
                 const float* __restrict__ Wih,   // L1: [C][G][1]; L2: [C][G][H]
                 const float* __restrict__ Whh,   // [C][G][H]
                 const float* __restrict__ bih,   // [C][G]
                 const float* __restrict__ bhh,   // [C][G]
                 const float* __restrict__ Wlin,  // [C][H]  (L2)
                 const float* __restrict__ blin,  // [C]     (L2)
                 float* __restrict__ out)         // [B][T][C] (L2)
{
    extern __shared__ float sm[];
    float* Whh_s  = sm;
    float* Wih_s  = Whh_s + 16384;
    float* h_s    = Wih_s + 16384;
    float* h1_s   = h_s   + 8192;
    float* parts  = h1_s  + 8192;
    float* wlin_s = parts + 4 * PBUF;
    float* wih1s  = wlin_s + 256;
    float* xs     = wih1s + 64;
    float* ored   = parts;           // alias: parts dead during head window

    const int tid   = threadIdx.x;
    const int c     = blockIdx.x >> 4;
    const int rank  = blockIdx.x & 15;
    const int jbase = rank << 4;

    // compute decomposition: warp = (rowgroup rg, k-quarter kq); lane = (rp, bh)
    const int warp = tid >> 5;
    const int lane = tid & 31;
    const int rg   = warp >> 2;         // rowgroup: rows 16rg..16rg+15
    const int kq   = warp & 3;          // k-quarter
    const int rp   = lane >> 2;         // row-pair within group
    const int bh   = lane & 3;          // batch octet
    const int r0   = 16 * rg + 2 * rp;  // local gate-row (even)
    const int bb   = bh * 8;            // first batch

    // activation decomposition (coalesced global stores)
    const int ab = tid & 31;            // batch = lane
    const int aj = tid >> 5;            // local hidden idx 0..15

    // ---- init: weights k-major, biases->regs, zero state ----
    for (int idx = tid; idx < 64 * Hv; idx += 512) {
        int k  = idx >> 6;
        int r  = idx & 63;
        int g  = r >> 4;
        int jl = r & 15;
        size_t grow = (size_t)c * Gv + g * Hv + (jbase + jl);
        Whh_s[k * 64 + r] = Whh[grow * Hv + k];
        if (LAYER == 2)
            Wih_s[k * 64 + r] = Wih[grow * Hv + k];
    }
    // per-thread bias for rows r0, r0+1 (added only by kq==0 accumulators)
    unsigned long long biasP0 = 0ull, biasP1 = 0ull;
    {
        int g0 = r0 >> 4, j0 = r0 & 15;
        size_t gi0 = (size_t)c * Gv + g0 * Hv + (jbase + j0);
        float b0f = bih[gi0] + bhh[gi0];
        float b1f = bih[gi0 + 1] + bhh[gi0 + 1];
        if (kq == 0) { PACK2(biasP0, b0f); PACK2(biasP1, b1f); }
    }
    if (LAYER == 1 && tid < 64) {
        int g = tid >> 4, jl = tid & 15;
        size_t gi = (size_t)c * Gv + g * Hv + (jbase + jl);
        wih1s[tid] = Wih[gi];
    }
    if (LAYER == 2 && tid < Hv) wlin_s[tid] = Wlin[c * Hv + tid];
    for (int i = tid; i < Hv * Bv; i += 512) h_s[i] = 0.0f;
    __syncthreads();

    const float blin_c = (LAYER == 2) ? __ldg(&blin[c]) : 0.0f;
    const unsigned h1s_addr = smem_u32(h1_s) + (unsigned)tid * 16u;

    // ---- prefetch step-0 inputs ----
    float xr = 0.0f;
    if (LAYER == 2) {
        const float* src = g_h1 + ((size_t)0 * Cv + c) * (Hv * Bv) + tid * 4;
        #pragma unroll
        for (int i = 0; i < 4; ++i) cp16(h1s_addr + i * 512u * 16u, src + i * 512 * 4);
        CP_COMMIT();
    } else {
        if (tid < Bv) xr = __ldg(&x[(size_t)tid * Tv * Cv + c]);
    }

    unsigned lsense = 0;
    float creg = 0.0f;                  // cell state (fixed per-thread mapping)

    for (int t = 0; t < Tv; ++t) {
        // ---- inputs ready ----
        if (LAYER == 2) {
            CP_WAIT0();
        } else {
            if (tid < Bv) xs[tid] = xr;
        }
        __syncthreads();   // h_s reload (prev step) + staged inputs visible

        // ---- gate mat-vecs: rows {r0,r0+1} x batches bb..bb+7 over k-quarter kq ----
        unsigned long long A[8], Bk[8];
        #pragma unroll
        for (int i = 0; i < 4; ++i) { A[i] = biasP0; A[4 + i] = biasP1; Bk[i] = 0ull; Bk[4 + i] = 0ull; }
        {
            const float* wh  = Whh_s + kq * 4096 + r0;
            const float* hpp = h_s   + kq * 2048 + bb;
            const float* wi  = Wih_s + kq * 4096 + r0;
            const float* ppp = h1_s  + kq * 2048 + bb;

            #pragma unroll 4
            for (int kk = 0; kk < 64; ++kk) {
                float2 wv = *(const float2*)wh;  wh += 64;
                unsigned long long w0, w1;
                PACK2(w0, wv.x); PACK2(w1, wv.y);
                ulonglong2 ha = *(const ulonglong2*)hpp;
                ulonglong2 hb = *(const ulonglong2*)(hpp + 4);  hpp += 32;
                FMA2(A[0], ha.x, w0); FMA2(A[1], ha.y, w0);
                FMA2(A[2], hb.x, w0); FMA2(A[3], hb.y, w0);
                FMA2(A[4], ha.x, w1); FMA2(A[5], ha.y, w1);
                FMA2(A[6], hb.x, w1); FMA2(A[7], hb.y, w1);

                if (LAYER == 2) {
                    float2 vv = *(const float2*)wi;  wi += 64;
                    unsigned long long v0, v1;
                    PACK2(v0, vv.x); PACK2(v1, vv.y);
                    ulonglong2 pa = *(const ulonglong2*)ppp;
                    ulonglong2 pb = *(const ulonglong2*)(ppp + 4);  ppp += 32;
                    FMA2(Bk[0], pa.x, v0); FMA2(Bk[1], pa.y, v0);
                    FMA2(Bk[2], pb.x, v0); FMA2(Bk[3], pb.y, v0);
                    FMA2(Bk[4], pa.x, v1); FMA2(Bk[5], pa.y, v1);
                    FMA2(Bk[6], pb.x, v1); FMA2(Bk[7], pb.y, v1);
                }
            }
        }
        if (LAYER == 2) {
            #pragma unroll
            for (int i = 0; i < 8; ++i) ADD2(A[i], A[i], Bk[i]);
        }

        // ---- store partials to this kq's buffer: [b][row], stride 66 ----
        {
            float* dst = parts + kq * PBUF;
            #pragma unroll
            for (int p = 0; p < 4; ++p) {
                int b = bb + 2 * p;
                float2 re = u2f(A[p]);      // (batch b, b+1), row r0
                float2 ro = u2f(A[4 + p]);  // row r0+1
                *(float2*)(dst + b * GSTR + r0)       = make_float2(re.x, ro.x);
                *(float2*)(dst + (b + 1) * GSTR + r0) = make_float2(re.y, ro.y);
            }
        }
        __syncthreads();   // sync1: partials ready, h1_s reads complete

        // ---- prefetch next step's inputs (h1_s dead until next loop top) ----
        if (LAYER == 2) {
            if (t + 1 < Tv) {
                const float* src = g_h1 + ((size_t)(t + 1) * Cv + c) * (Hv * Bv) + tid * 4;
                #pragma unroll
                for (int i = 0; i < 4; ++i) cp16(h1s_addr + i * 512u * 16u, src + i * 512 * 4);
                CP_COMMIT();
            }
        } else {
            if (tid < Bv && t + 1 < Tv)
                xr = __ldg(&x[(size_t)tid * Tv * Cv + (t + 1) * Cv + c]);
        }

        // ---- activations + state update: thread -> (b = lane, j = warp) ----
        {
            const float* pr = parts + ab * GSTR;
            float vi = pr[          aj] + pr[PBUF +          aj] + pr[2*PBUF +          aj] + pr[3*PBUF +          aj];
            float vf = pr[16 +      aj] + pr[PBUF + 16 +      aj] + pr[2*PBUF + 16 +      aj] + pr[3*PBUF + 16 +      aj];
            float vg = pr[32 +      aj] + pr[PBUF + 32 +      aj] + pr[2*PBUF + 32 +      aj] + pr[3*PBUF + 32 +      aj];
            float vo = pr[48 +      aj] + pr[PBUF + 48 +      aj] + pr[2*PBUF + 48 +      aj] + pr[3*PBUF + 48 +      aj];
            if (LAYER == 1) {
                float xv = xs[ab];
                vi = fmaf(xv, wih1s[     aj], vi);
                vf = fmaf(xv, wih1s[16 + aj], vf);
                vg = fmaf(xv, wih1s[32 + aj], vg);
                vo = fmaf(xv, wih1s[48 + aj], vo);
            }
            float iv = sig_(vi), fv = sig_(vf), gv = tanh_(vg), ov = sig_(vo);
            float cn = fmaf(fv, creg, iv * gv);
            creg = cn;
            float hn = ov * tanh_(cn);
            size_t hoff = ((size_t)c * Hv + jbase + aj) * Bv + ab;   // coalesced
            g_hbuf[(size_t)(t & 1) * (Cv * Hv * Bv) + hoff] = hn;
            if (LAYER == 1)
                g_h1[(((size_t)t * Cv + c) * Hv + jbase + aj) * Bv + ab] = hn;
        }

        chan_barrier(c, lsense);

        // ---- reload full h[t] for this channel into h_s[k][b] ----
        {
            const float4* src = (const float4*)(g_hbuf + (size_t)(t & 1) * (Cv * Hv * Bv)
                                                        + (size_t)c * Hv * Bv);
            float4* dst = (float4*)h_s;
            #pragma unroll
            for (int i = 0; i < 4; ++i)
                dst[tid + i * 512] = __ldcg(src + tid + i * 512);
        }

        // ---- final linear head (layer2, rank-0 CTA); ored aliases parts (dead here) ----
        if (LAYER == 2 && rank == 0) {
            __syncthreads();     // h_s reload visible
            if (tid < 256) {
                int w = tid >> 5, b = tid & 31;
                const float* hp = h_s + w * 32 * 32 + b;
                const float* wl = wlin_s + w * 32;
                float s = 0.0f;
                #pragma unroll
                for (int k2 = 0; k2 < 32; ++k2)
                    s = fmaf(hp[k2 * 32], wl[k2], s);
                ored[w * 32 + b] = s;
            }
            __syncthreads();
            if (tid < 32) {
                float s = blin_c;
                #pragma unroll
                for (int w = 0; w < 8; ++w) s += ored[w * 32 + tid];
                out[(size_t)tid * Tv * Cv + t * Cv + c] = s;
            }
        }
        // loop-top __syncthreads orders h_s reload (and ored/parts reuse) before next compute
    }
}

// ---------------- launch ----------------
extern "C" void kernel_launch(void* const* d_in, const int* in_sizes, int n_in,
                              void* d_out, int out_size)
{
    const float* x    = (const float*)d_in[0];
    const float* Wih1 = (const float*)d_in[1];
    const float* Whh1 = (const float*)d_in[2];
    const float* bih1 = (const float*)d_in[3];
    const float* bhh1 = (const float*)d_in[4];
    const float* Wih2 = (const float*)d_in[5];
    const float* Whh2 = (const float*)d_in[6];
    const float* bih2 = (const float*)d_in[7];
    const float* bhh2 = (const float*)d_in[8];
    const float* Wlin = (const float*)d_in[9];
    const float* blin = (const float*)d_in[10];
    float* out = (float*)d_out;

    (void)in_sizes; (void)n_in; (void)out_size;

    cudaFuncSetAttribute(lstm_kernel<1>, cudaFuncAttributeMaxDynamicSharedMemorySize, SM_BYTES);
    cudaFuncSetAttribute(lstm_kernel<2>, cudaFuncAttributeMaxDynamicSharedMemorySize, SM_BYTES);

    lstm_kernel<1><<<128, 512, SM_BYTES>>>(x, Wih1, Whh1, bih1, bhh1,
                                           nullptr, nullptr, nullptr);
    lstm_kernel<2><<<128, 512, SM_BYTES>>>(nullptr, Wih2, Whh2, bih2, bhh2,
                                           Wlin, blin, out);
}